// round 9
// baseline (speedup 1.0000x reference)
#include <cuda_runtime.h>

// Problem constants (fixed: B=16, N=8192, C=256, num_points=2048)
#define BB   16
#define NN   8192
#define CC   256
#define MM   2048
#define TT   1024          // threads per FPS block
#define PPT  (NN / TT)     // points per thread = 8
#define NPAIR (PPT / 2)    // f32x2 pairs per thread = 4

// Scratch: selected indices, written by FPS kernel, read by gather kernel.
__device__ int g_idx[BB * MM];

// Dynamic smem: sq4[NN] float4 | pvi[64] uint2 | initv[32] | initi[32] |
//               cent[96] | cmn[96] | cmx[96] | skx[NN] uint | ski[NN] int
#define SMEM_BYTES (NN * 16 + 64 * 8 + 32 * 4 + 32 * 4 + 3 * 96 * 4 + NN * 4 + NN * 4)

// ---- packed f32x2 helpers (sm_103a) ---------------------------------------
__device__ __forceinline__ unsigned long long pack2(float lo, float hi) {
    unsigned long long r;
    asm("mov.b64 %0, {%1, %2};" : "=l"(r) : "f"(lo), "f"(hi));
    return r;
}
__device__ __forceinline__ void unpack2(unsigned long long v, float& lo, float& hi) {
    asm("mov.b64 {%0, %1}, %2;" : "=f"(lo), "=f"(hi) : "l"(v));
}
__device__ __forceinline__ unsigned long long add2(unsigned long long a, unsigned long long b) {
    unsigned long long r;
    asm("add.rn.f32x2 %0, %1, %2;" : "=l"(r) : "l"(a), "l"(b));
    return r;
}
__device__ __forceinline__ unsigned long long mul2(unsigned long long a, unsigned long long b) {
    unsigned long long r;
    asm("mul.rn.f32x2 %0, %1, %2;" : "=l"(r) : "l"(a), "l"(b));
    return r;
}
// ---------------------------------------------------------------------------

__device__ __forceinline__ float warp_sum(float x) {
    #pragma unroll
    for (int o = 16; o > 0; o >>= 1)
        x += __shfl_xor_sync(0xFFFFFFFFu, x, o);
    return x;
}
__device__ __forceinline__ float warp_min(float x) {
    #pragma unroll
    for (int o = 16; o > 0; o >>= 1)
        x = fminf(x, __shfl_xor_sync(0xFFFFFFFFu, x, o));
    return x;
}
__device__ __forceinline__ float warp_max(float x) {
    #pragma unroll
    for (int o = 16; o > 0; o >>= 1)
        x = fmaxf(x, __shfl_xor_sync(0xFFFFFFFFu, x, o));
    return x;
}

// Expand 10 bits to every 3rd bit (Morton).
__device__ __forceinline__ unsigned expand10(unsigned v) {
    v = (v | (v << 16)) & 0x030000FFu;
    v = (v | (v <<  8)) & 0x0300F00Fu;
    v = (v | (v <<  4)) & 0x030C30C3u;
    v = (v | (v <<  2)) & 0x09249249u;
    return v;
}

extern "C" __global__ void __launch_bounds__(TT, 1)
fps_kernel(const float* __restrict__ pts,   // [B, 3, N]
           float* __restrict__ out_pts)     // [B, M, 3]
{
    extern __shared__ unsigned char smraw[];
    float4*   sq4   = (float4*)smraw;                  // [NN] orig-indexed coords
    uint2*    pvi   = (uint2*)(smraw + NN * 16);       // [64] (val,cand), 2 bufs
    unsigned* initv = (unsigned*)(pvi + 64);           // [32]
    unsigned* initi = initv + 32;                      // [32]
    float*    cent  = (float*)(initi + 32);            // [96] sum partials
    float*    cmn   = cent + 96;                       // [96] min partials
    float*    cmx   = cmn + 96;                        // [96] max partials
    unsigned* skx   = (unsigned*)(cmx + 96);           // [NN] Morton keys
    int*      ski   = (int*)(skx + NN);                // [NN] orig indices

    const int b    = blockIdx.x;
    const int tid  = threadIdx.x;
    const int lane = tid & 31;
    const int warp = tid >> 5;

    const float* px = pts + (size_t)b * 3 * NN;
    const float* py = px + NN;
    const float* pz = px + 2 * NN;

    // ---- load (orig layout); per-thread sums + global bbox partials ----
    float s1 = 0.f, s2 = 0.f, s3 = 0.f;
    float lmnx = 1e30f, lmxx = -1e30f, lmny = 1e30f, lmxy = -1e30f;
    float lmnz = 1e30f, lmxz = -1e30f;
    float xl[PPT], yl[PPT], zl[PPT];
    #pragma unroll
    for (int k = 0; k < PPT; k++) {
        int n = tid + k * TT;               // coalesced
        float x = px[n], y = py[n], z = pz[n];
        xl[k] = x; yl[k] = y; zl[k] = z;
        sq4[n] = make_float4(x, y, z, 0.f);
        s1 += x; s2 += y; s3 += z;
        lmnx = fminf(lmnx, x); lmxx = fmaxf(lmxx, x);
        lmny = fminf(lmny, y); lmxy = fmaxf(lmxy, y);
        lmnz = fminf(lmnz, z); lmxz = fmaxf(lmxz, z);
    }
    s1 = warp_sum(s1); s2 = warp_sum(s2); s3 = warp_sum(s3);
    lmnx = warp_min(lmnx); lmxx = warp_max(lmxx);
    lmny = warp_min(lmny); lmxy = warp_max(lmxy);
    lmnz = warp_min(lmnz); lmxz = warp_max(lmxz);
    if (lane == 0) {
        cent[warp] = s1; cent[32 + warp] = s2; cent[64 + warp] = s3;
        cmn[warp] = lmnx; cmn[32 + warp] = lmny; cmn[64 + warp] = lmnz;
        cmx[warp] = lmxx; cmx[32 + warp] = lmxy; cmx[64 + warp] = lmxz;
    }
    __syncthreads();

    // Global bbox + centroid (every warp computes identically).
    float gmnx = warp_min(cmn[lane]);
    float gmny = warp_min(cmn[32 + lane]);
    float gmnz = warp_min(cmn[64 + lane]);
    float gmxx = warp_max(cmx[lane]);
    float gmxy = warp_max(cmx[32 + lane]);
    float gmxz = warp_max(cmx[64 + lane]);
    float cx = warp_sum(cent[lane])      * (1.0f / NN);
    float cy = warp_sum(cent[32 + lane]) * (1.0f / NN);
    float cz = warp_sum(cent[64 + lane]) * (1.0f / NN);

    float sxsc = 1023.0f / fmaxf(gmxx - gmnx, 1e-20f);
    float sysc = 1023.0f / fmaxf(gmxy - gmny, 1e-20f);
    float szsc = 1023.0f / fmaxf(gmxz - gmnz, 1e-20f);

    // ---- Morton keys (sort quality only affects pruning, never correctness) ----
    #pragma unroll
    for (int k = 0; k < PPT; k++) {
        int n = tid + k * TT;
        unsigned xi = (unsigned)fminf(fmaxf((xl[k] - gmnx) * sxsc, 0.f), 1023.f);
        unsigned yi = (unsigned)fminf(fmaxf((yl[k] - gmny) * sysc, 0.f), 1023.f);
        unsigned zi = (unsigned)fminf(fmaxf((zl[k] - gmnz) * szsc, 0.f), 1023.f);
        skx[n] = (expand10(xi) << 2) | (expand10(yi) << 1) | expand10(zi);
        ski[n] = n;
    }

    // ---- bitonic sort by Morton key (permutation-preserving) ----
    for (int k = 2; k <= NN; k <<= 1) {
        for (int j = k >> 1; j > 0; j >>= 1) {
            __syncthreads();
            #pragma unroll 4
            for (int t = tid; t < NN / 2; t += TT) {
                int i = 2 * t - (t & (j - 1));
                int l = i + j;
                bool up = ((i & k) == 0);
                unsigned a = skx[i], c = skx[l];
                bool sw = up ? (a > c) : (a < c);
                if (sw) {
                    skx[i] = c; skx[l] = a;
                    int ta = ski[i]; ski[i] = ski[l]; ski[l] = ta;
                }
            }
        }
    }
    __syncthreads();

    // ---- reorder into registers: warp w owns Morton ranks [256w, 256w+256) ----
    unsigned long long X2[NPAIR], Y2[NPAIR], Z2[NPAIR];
    unsigned OI2[NPAIR];                    // packed orig indices (lo | hi<<16)
    float dr[PPT];
    float xs[PPT], ys[PPT], zs[PPT];
    unsigned oi[PPT];
    const int base = warp * 256 + lane;
    #pragma unroll
    for (int k = 0; k < PPT; k++) {
        int r = base + 32 * k;
        int idx = ski[r];
        float4 p = sq4[idx];
        xs[k] = p.x; ys[k] = p.y; zs[k] = p.z;
        oi[k] = (unsigned)idx;
        dr[k] = 1e10f;
    }
    #pragma unroll
    for (int j = 0; j < NPAIR; j++) {
        X2[j] = pack2(xs[2 * j], xs[2 * j + 1]);
        Y2[j] = pack2(ys[2 * j], ys[2 * j + 1]);
        Z2[j] = pack2(zs[2 * j], zs[2 * j + 1]);
        OI2[j] = oi[2 * j] | (oi[2 * j + 1] << 16);
    }
    // Warp bbox (from the points this warp actually holds -> always safe).
    float xmn = xs[0], xmx = xs[0], ymn = ys[0], ymx = ys[0], zmn = zs[0], zmx = zs[0];
    #pragma unroll
    for (int k = 1; k < PPT; k++) {
        xmn = fminf(xmn, xs[k]); xmx = fmaxf(xmx, xs[k]);
        ymn = fminf(ymn, ys[k]); ymx = fmaxf(ymx, ys[k]);
        zmn = fminf(zmn, zs[k]); zmx = fmaxf(zmx, zs[k]);
    }
    xmn = warp_min(xmn); xmx = warp_max(xmx);
    ymn = warp_min(ymn); ymx = warp_max(ymx);
    zmn = warp_min(zmn); zmx = warp_max(zmx);

    // d0 = ||p - centroid||^2, initial farthest (exact plain form; orig-idx
    // tie-break since held points are no longer index-ordered).
    float best = -1.0f; unsigned bi = 0xFFFFFFFFu;
    #pragma unroll
    for (int k = 0; k < PPT; k++) {
        float dx = xs[k] - cx, dy = ys[k] - cy, dz = zs[k] - cz;
        float d = __fadd_rn(__fadd_rn(__fmul_rn(dx, dx), __fmul_rn(dy, dy)),
                            __fmul_rn(dz, dz));
        if (d > best)            { best = d; bi = oi[k]; }
        else if (d == best && oi[k] < bi) bi = oi[k];
    }
    {
        unsigned vb = __float_as_uint(best);
        unsigned m1 = __reduce_max_sync(0xFFFFFFFFu, vb);
        unsigned c1 = (vb == m1) ? bi : 0xFFFFFFFFu;
        unsigned i1 = __reduce_min_sync(0xFFFFFFFFu, c1);
        if (lane == 0) { initv[warp] = m1; initi[warp] = i1; }
    }
    __syncthreads();
    unsigned far;
    {
        unsigned v2 = initv[lane];
        unsigned i2 = initi[lane];
        unsigned m2 = __reduce_max_sync(0xFFFFFFFFu, v2);
        unsigned c2 = (v2 == m2) ? i2 : 0xFFFFFFFFu;
        far = __reduce_min_sync(0xFFFFFFFFu, c2);
    }

    float* outp = out_pts + (size_t)b * MM * 3;
    int*   idxp = g_idx + b * MM;

    // Per-warp cached state: exact max-dr bits + min orig idx among ties.
    // Valid while the warp skips updates (dr unchanged). First iteration
    // always updates (bnd < 1e10), which initializes wcand properly.
    unsigned wvb   = __float_as_uint(1e10f);
    unsigned wcand = 0xFFFFFFFFu;

    for (int m = 0; m < MM; m++) {
        const int buf = m & 1;
        // Broadcast the selected point (one LDS.128, orig-indexed table).
        float4 q = sq4[far];
        if (tid == 0) {
            idxp[m] = (int)far;
            outp[m * 3 + 0] = q.x;
            outp[m * 3 + 1] = q.y;
            outp[m * 3 + 2] = q.z;
        }

        // Bbox prune: if 0.99999*dist2(q, bbox) >= warp max dr, the min-update
        // is a bit-level no-op for every point this warp holds -> dr, wvb,
        // wcand all keep their exact values.
        float gx = fmaxf(fmaxf(xmn - q.x, q.x - xmx), 0.0f);
        float gy = fmaxf(fmaxf(ymn - q.y, q.y - ymx), 0.0f);
        float gz = fmaxf(fmaxf(zmn - q.z, q.z - zmx), 0.0f);
        float bnd = 0.99999f * (gx * gx + gy * gy + gz * gz);
        if (bnd < __uint_as_float(wvb)) {
            // Exact update (reference-rounded, no contraction).
            unsigned long long nqx2 = pack2(-q.x, -q.x);
            unsigned long long nqy2 = pack2(-q.y, -q.y);
            unsigned long long nqz2 = pack2(-q.z, -q.z);
            #pragma unroll
            for (int j = 0; j < NPAIR; j++) {
                unsigned long long dx2 = add2(X2[j], nqx2);
                unsigned long long dy2 = add2(Y2[j], nqy2);
                unsigned long long dz2 = add2(Z2[j], nqz2);
                unsigned long long d2 = add2(add2(mul2(dx2, dx2), mul2(dy2, dy2)),
                                             mul2(dz2, dz2));
                float dlo, dhi;
                unpack2(d2, dlo, dhi);
                dr[2 * j]     = fminf(dr[2 * j],     dlo);
                dr[2 * j + 1] = fminf(dr[2 * j + 1], dhi);
            }
            float a0 = fmaxf(dr[0], dr[1]);
            float a1 = fmaxf(dr[2], dr[3]);
            float a2 = fmaxf(dr[4], dr[5]);
            float a3 = fmaxf(dr[6], dr[7]);
            float mx = fmaxf(fmaxf(a0, a1), fmaxf(a2, a3));
            wvb = __reduce_max_sync(0xFFFFFFFFu, __float_as_uint(mx));
            // Min original index among bit-equal maxima (this warp).
            unsigned cand = 0xFFFFFFFFu;
            #pragma unroll
            for (int j = 0; j < NPAIR; j++) {
                if (__float_as_uint(dr[2 * j])     == wvb)
                    cand = min(cand, OI2[j] & 0xFFFFu);
                if (__float_as_uint(dr[2 * j + 1]) == wvb)
                    cand = min(cand, OI2[j] >> 16);
            }
            wcand = __reduce_min_sync(0xFFFFFFFFu, cand);
        }

        // Single-barrier block argmax over the 32 cached (wvb, wcand) pairs.
        if (lane == 0) pvi[buf * 32 + warp] = make_uint2(wvb, wcand);
        __syncthreads();
        uint2 p2 = pvi[buf * 32 + lane];                 // LDS.64
        unsigned m2 = __reduce_max_sync(0xFFFFFFFFu, p2.x);
        unsigned c2 = (p2.x == m2) ? p2.y : 0xFFFFFFFFu;
        far = __reduce_min_sync(0xFFFFFFFFu, c2);
    }
}

// Gather with channel-tiled blocks (indices preloaded to smem; coalesced
// writes; channel-plane reads get L1/L2 reuse).
#define CT 32            // channels per block
#define MT 512           // samples per block
extern "C" __global__ void __launch_bounds__(256)
gather_kernel(const float* __restrict__ feats,  // [B, C, N]
              float* __restrict__ out_feats)    // [B, M, C]
{
    __shared__ int sn[MT];
    int blk = blockIdx.x;                    // b * 32 + ct * 4 + mt
    int b   = blk >> 5;
    int ct  = (blk >> 2) & 7;                // 8 channel tiles
    int mt  = blk & 3;                       // 4 sample tiles
    int tid = threadIdx.x;

    for (int i = tid; i < MT; i += 256)
        sn[i] = g_idx[b * MM + mt * MT + i];
    __syncthreads();

    int c  = ct * CT + (tid & 31);
    int ml = tid >> 5;                       // 0..7
    const float* fp = feats + ((size_t)b * CC + c) * NN;
    float* op = out_feats + ((size_t)b * MM + mt * MT) * CC + c;

    #pragma unroll 4
    for (int mm = ml; mm < MT; mm += 8)
        op[(size_t)mm * CC] = fp[sn[mm]];
}

// Tiny kernel to keep ncu's "-s 5 -c 1" window on fps_kernel.
extern "C" __global__ void warm_kernel() {}

extern "C" void kernel_launch(void* const* d_in, const int* in_sizes, int n_in,
                              void* d_out, int out_size)
{
    const float* pts   = (const float*)d_in[0];  // [B, 3, N]
    const float* feats = (const float*)d_in[1];  // [B, C, N]
    float* out = (float*)d_out;

    cudaFuncSetAttribute(fps_kernel,
                         cudaFuncAttributeMaxDynamicSharedMemorySize, SMEM_BYTES);

    fps_kernel<<<BB, TT, SMEM_BYTES>>>(pts, out);
    warm_kernel<<<1, 1>>>();
    gather_kernel<<<BB * 32, 256>>>(feats, out + (size_t)BB * MM * 3);
}